// round 3
// baseline (speedup 1.0000x reference)
#include <cuda_runtime.h>
#include <math_constants.h>

// CenterNet decode, sm_100a.
// d_in[0]=fmap f32 [32,80,128,128], d_in[1]=wh f32 [32,2,128,128],
// d_in[2]=reg f32 [32,2,128,128], d_in[3]=K (=100)
// out f32: concat(bboxes[32,100,4], scores[32,100,1], clses[32,100,1]) = 19200

#define NB 32
#define NC 80
#define NH 128
#define NW 128
#define NHW 16384
#define NK 100
#define CK 8000
#define CAP 4096        // per-(b,c) survivor cap (strict kings-graph IS <= 4096)
#define SORT_CAP 512    // candidate sort capacity
#define NBINS 2048

typedef unsigned long long u64;
typedef unsigned int u32;

__device__ float g_score[NB * CK];
__device__ int   g_sidx[NB * CK];

extern __shared__ unsigned char smem_raw[];

// (value desc, index asc) packed into one descending-sortable u64; v >= 0 so
// float bits are order-preserving.
__device__ __forceinline__ u64 pack_key(float v, int idx) {
    return ((u64)__float_as_uint(v) << 32) | (u32)(65535 - idx);
}

__device__ __forceinline__ void bitonic_sort_desc(u64* keys, int n, int tid, int nth) {
    for (int k = 2; k <= n; k <<= 1) {
        for (int j = k >> 1; j > 0; j >>= 1) {
            for (int i = tid; i < n; i += nth) {
                int l = i ^ j;
                if (l > i) {
                    u64 a = keys[i], b = keys[l];
                    bool desc = ((i & k) == 0);
                    if (desc ? (a < b) : (a > b)) { keys[i] = b; keys[l] = a; }
                }
            }
            __syncthreads();
        }
    }
}

// Find threshold bin T (descending scan over NBINS=2048 bins) such that
// count(bins > T) < need <= count(bins >= T). Requires blockDim.x == 512.
// Writes *sh_T and *sh_above (= count in bins strictly > T).
__device__ void hist_threshold(const u32* hist, int need, int tid, int* sh_T, int* sh_above) {
    __shared__ int warp_pref[16];
    int base = 2047 - 4 * tid;
    int h0 = hist[base], h1 = hist[base - 1], h2 = hist[base - 2], h3 = hist[base - 3];
    int gs = h0 + h1 + h2 + h3;
    int lane = tid & 31, w = tid >> 5;
    int v = gs;
    #pragma unroll
    for (int off = 1; off < 32; off <<= 1) {
        int u = __shfl_up_sync(0xffffffffu, v, off);
        if (lane >= off) v += u;
    }
    if (lane == 31) warp_pref[w] = v;
    __syncthreads();
    if (w == 0) {
        int x = (lane < 16) ? warp_pref[lane] : 0;
        #pragma unroll
        for (int off = 1; off < 16; off <<= 1) {
            int u = __shfl_up_sync(0xffffffffu, x, off);
            if (lane >= off) x += u;
        }
        if (lane < 16) warp_pref[lane] = x;
    }
    __syncthreads();
    int pref = v + (w ? warp_pref[w - 1] : 0);   // count of bins >= base-3
    int before = pref - gs;                       // count of bins >  base
    if (pref >= need && before < need) {
        int run = before;
        int hh[4] = {h0, h1, h2, h3};
        #pragma unroll
        for (int i = 0; i < 4; i++) {
            if (run + hh[i] >= need) { *sh_T = base - i; *sh_above = run; break; }
            run += hh[i];
        }
    }
    if (tid == 511 && pref < need) { *sh_T = 0; *sh_above = pref - h3; }
    __syncthreads();
}

// Select a superset of the top-K keys from surv[0..n) into cand (level-1 hist
// on bits[31:21] of the value prebuilt in hist). Returns candidate count, or
// -1 => caller must fall back to a full sort of surv.
__device__ int select_candidates(u64* surv, int n, u32* hist, u64* cand,
                                 int K, int tid, int nth) {
    __shared__ int sh_T, sh_above, sh_cnt, sh_T2, sh_above2;
    if (n <= SORT_CAP) {
        for (int i = tid; i < n; i += nth) cand[i] = surv[i];
        __syncthreads();
        return n;
    }
    hist_threshold(hist, K, tid, &sh_T, &sh_above);
    int T1 = sh_T, A = sh_above;
    int E1 = hist[T1];
    if (tid == 0) sh_cnt = 0;
    __syncthreads();
    if (A + E1 <= SORT_CAP) {
        for (int i = tid; i < n; i += nth) {
            u64 key = surv[i];
            if ((int)((u32)(key >> 32) >> 21) >= T1) {
                int p = atomicAdd(&sh_cnt, 1);
                cand[p] = key;
            }
        }
        __syncthreads();
        return sh_cnt;
    }
    // level 2: refine within bin T1 on value bits [20:10]
    for (int i = tid; i < NBINS; i += nth) hist[i] = 0;
    __syncthreads();
    for (int i = tid; i < n; i += nth) {
        u64 key = surv[i];
        u32 vb = (u32)(key >> 32);
        if ((int)(vb >> 21) == T1) atomicAdd(&hist[(vb >> 10) & 0x7FF], 1);
    }
    __syncthreads();
    hist_threshold(hist, K - A, tid, &sh_T2, &sh_above2);
    int T2 = sh_T2, A2 = sh_above2;
    int E2 = hist[T2];
    if (A + A2 + E2 > SORT_CAP) return -1;  // pathological ties: full sort
    for (int i = tid; i < n; i += nth) {
        u64 key = surv[i];
        u32 vb = (u32)(key >> 32);
        int b1 = vb >> 21;
        bool take = (b1 > T1) || (b1 == T1 && (int)((vb >> 10) & 0x7FF) >= T2);
        if (take) { int p = atomicAdd(&sh_cnt, 1); cand[p] = key; }
    }
    __syncthreads();
    return sh_cnt;
}

// Sort candidates (or fall back to sorting surv) and return pointer to the
// descending-sorted result (first NK entries valid; zero-padded).
__device__ u64* finalize_sort(u64* surv, int n, u64* cand, int cnt, int tid, int nth) {
    if (cnt < 0) {
        int np = 128; while (np < n) np <<= 1;
        for (int i = n + tid; i < np; i += nth) surv[i] = 0ULL;
        __syncthreads();
        bitonic_sort_desc(surv, np, tid, nth);
        return surv;
    }
    int np = 128; while (np < cnt) np <<= 1;
    for (int i = cnt + tid; i < np; i += nth) cand[i] = 0ULL;
    __syncthreads();
    bitonic_sort_desc(cand, np, tid, nth);
    return cand;
}

// ---------------------------------------------------------------------------
// Kernel 1: per-(b,c) pseudo-NMS + top-100 select. Grid = B*C = 2560 blocks.
// smem: surv[4096] u64 (32K) + hist[2048] u32 (8K) + cand[512] u64 (4K) = 44K
// ---------------------------------------------------------------------------
__global__ void __launch_bounds__(512) k_topk_per_class(const float* __restrict__ fmap) {
    u64* s_surv = (u64*)smem_raw;
    u32* s_hist = (u32*)(s_surv + CAP);
    u64* s_cand = (u64*)(s_hist + NBINS);
    __shared__ int s_cnt;

    const int bc = blockIdx.x;
    const int tid = threadIdx.x;
    const float* __restrict__ f = fmap + (size_t)bc * NHW;

    for (int i = tid; i < NBINS; i += 512) s_hist[i] = 0;
    if (tid == 0) s_cnt = 0;
    __syncthreads();

    // NMS: thread = 32 consecutive x's in row r; rolling column-max window.
    // keep p iff max(3x3 window incl. center) == center  (== v >= all neighbors)
    const int r = tid & 127;
    const int seg = (tid >> 7) << 5;
    const float* rowc = f + r * NW;
    const float* rowm = rowc - NW;
    const float* rowp = rowc + NW;
    const bool hm = (r > 0), hp = (r < NH - 1);

    auto CM = [&](int x, float& cen) -> float {
        float c = __ldg(rowc + x);
        cen = c;
        float m = c;
        if (hm) m = fmaxf(m, __ldg(rowm + x));
        if (hp) m = fmaxf(m, __ldg(rowp + x));
        return m;
    };

    float dummy, v_cur, v_next = 0.0f;
    float cm_prev = (seg > 0) ? CM(seg - 1, dummy) : -CUDART_INF_F;
    float cm_cur  = CM(seg, v_cur);
    #pragma unroll 4
    for (int i = 0; i < 32; i++) {
        int x = seg + i;
        float cm_next = (x + 1 < NW) ? CM(x + 1, v_next) : -CUDART_INF_F;
        float win = fmaxf(cm_prev, fmaxf(cm_cur, cm_next));
        if (win == v_cur) {
            int p = atomicAdd(&s_cnt, 1);
            if (p < CAP) {
                s_surv[p] = pack_key(v_cur, r * NW + x);
                atomicAdd(&s_hist[__float_as_uint(v_cur) >> 21], 1);
            }
        }
        cm_prev = cm_cur; cm_cur = cm_next; v_cur = v_next;
    }
    __syncthreads();

    int n = min(s_cnt, CAP);
    int cnt = select_candidates(s_surv, n, s_hist, s_cand, NK, tid, 512);
    u64* res = finalize_sort(s_surv, n, s_cand, cnt, tid, 512);

    if (tid < NK) {
        u64 key = res[tid];
        float sc; int idx;
        if (key == 0ULL) { sc = 0.0f; idx = 0; }
        else { sc = __uint_as_float((u32)(key >> 32)); idx = 65535 - (int)(key & 0xFFFFu); }
        g_score[(size_t)bc * NK + tid] = sc;
        g_sidx[(size_t)bc * NK + tid]  = idx;
    }
}

// ---------------------------------------------------------------------------
// Kernel 2: per-batch global top-100 over C*K=8000 + box decode. Grid = B.
// smem: surv[8192] u64 (64K) + hist[2048] u32 (8K) + cand[512] u64 (4K) = 76K
// ---------------------------------------------------------------------------
__global__ void __launch_bounds__(512) k_topk_global(const float* __restrict__ wh,
                                                     const float* __restrict__ reg,
                                                     float* __restrict__ out) {
    u64* s_surv = (u64*)smem_raw;
    u32* s_hist = (u32*)(s_surv + 8192);
    u64* s_cand = (u64*)(s_hist + NBINS);

    const int b = blockIdx.x;
    const int tid = threadIdx.x;

    for (int i = tid; i < NBINS; i += 512) s_hist[i] = 0;
    __syncthreads();
    for (int j = tid; j < CK; j += 512) {
        float sc = g_score[(size_t)b * CK + j];
        u32 vb = __float_as_uint(sc);
        s_surv[j] = ((u64)vb << 32) | (u32)(65535 - j);
        atomicAdd(&s_hist[vb >> 21], 1);
    }
    __syncthreads();

    int cnt = select_candidates(s_surv, CK, s_hist, s_cand, NK, tid, 512);
    u64* res = finalize_sort(s_surv, CK, s_cand, cnt, tid, 512);

    const float* __restrict__ whb = wh + (size_t)b * 2 * NHW;
    const float* __restrict__ rgb = reg + (size_t)b * 2 * NHW;

    if (tid < NK) {
        u64 key = res[tid];
        float sc = __uint_as_float((u32)(key >> 32));
        int j = 65535 - (int)(key & 0xFFFFu);
        float bx0 = 0.f, by0 = 0.f, bx1 = 0.f, by1 = 0.f, cls = 0.f;
        if (key != 0ULL && j >= 0 && j < CK) {
            int c = j / NK;
            int sp = g_sidx[(size_t)b * CK + j];
            float ys = (float)(sp >> 7);
            float xs = (float)(sp & 127);
            float xc = xs + __ldg(rgb + sp);
            float yc = ys + __ldg(rgb + NHW + sp);
            float hw2 = 0.5f * __ldg(whb + sp);
            float hh2 = 0.5f * __ldg(whb + NHW + sp);
            bx0 = xc - hw2; by0 = yc - hh2; bx1 = xc + hw2; by1 = yc + hh2;
            cls = (float)c;
        } else {
            sc = 0.f;
        }
        size_t bb = ((size_t)b * NK + tid) * 4;
        out[bb + 0] = bx0;
        out[bb + 1] = by0;
        out[bb + 2] = bx1;
        out[bb + 3] = by1;
        out[(size_t)NB * NK * 4 + (size_t)b * NK + tid] = sc;
        out[(size_t)NB * NK * 5 + (size_t)b * NK + tid] = cls;
    }
}

extern "C" void kernel_launch(void* const* d_in, const int* in_sizes, int n_in,
                              void* d_out, int out_size) {
    const float* fmap = (const float*)d_in[0];
    const float* wh   = (const float*)d_in[1];
    const float* reg  = (const float*)d_in[2];
    float* out = (float*)d_out;

    const size_t smem1 = CAP * 8 + NBINS * 4 + SORT_CAP * 8;          // 44 KB
    const size_t smem2 = 8192 * 8 + NBINS * 4 + SORT_CAP * 8;         // 76 KB

    static bool attr_done = false;
    if (!attr_done) {
        cudaFuncSetAttribute(k_topk_per_class, cudaFuncAttributeMaxDynamicSharedMemorySize, (int)smem1);
        cudaFuncSetAttribute(k_topk_global,    cudaFuncAttributeMaxDynamicSharedMemorySize, (int)smem2);
        attr_done = true;
    }

    k_topk_per_class<<<NB * NC, 512, smem1>>>(fmap);
    k_topk_global<<<NB, 512, smem2>>>(wh, reg, out);
}

// round 4
// speedup vs baseline: 7.2071x; 7.2071x over previous
#include <cuda_runtime.h>

// CenterNet decode, sm_100a.
// d_in[0]=fmap f32 [32,80,128,128], d_in[1]=wh f32 [32,2,128,128],
// d_in[2]=reg f32 [32,2,128,128], d_in[3]=K (=100)
// out f32: concat(bboxes[32,100,4], scores[32,100,1], clses[32,100,1]) = 19200

#define NB 32
#define NC 80
#define NHW 16384
#define NK 100
#define GCAP 8192
#define TAU0 0.999f

typedef unsigned long long u64;
typedef unsigned int u32;

__device__ u64 g_cand[NB * GCAP];
__device__ int g_cnt[NB];

extern __shared__ unsigned char smem_raw[];

// monotone float->uint mapping (handles negatives too)
__device__ __forceinline__ u32 ord32(float f) {
    u32 b = __float_as_uint(f);
    return b ^ ((u32)((int)b >> 31) | 0x80000000u);
}
__device__ __forceinline__ float ord_inv(u32 o) {
    u32 b = (o & 0x80000000u) ? (o ^ 0x80000000u) : ~o;
    return __uint_as_float(b);
}
// key: (score desc, class asc, spatial idx asc) as one descending u64
__device__ __forceinline__ u64 make_key(float v, int c, int p) {
    return ((u64)ord32(v) << 32) |
           (u32)(((NC - 1 - c) << 14) | (NHW - 1 - p));
}

// keep iff v >= all in-bounds 8-neighbors (== maxpool3x3(-inf pad) == v)
__device__ __forceinline__ bool nms_keep(const float* __restrict__ f, int p, float v) {
    const int y = p >> 7, x = p & 127;
    if (y > 0) {
        const float* r = f + p - 128;
        if (x > 0   && v < __ldg(r - 1)) return false;
        if (           v < __ldg(r))     return false;
        if (x < 127 && v < __ldg(r + 1)) return false;
    }
    if (x > 0   && v < __ldg(f + p - 1)) return false;
    if (x < 127 && v < __ldg(f + p + 1)) return false;
    if (y < 127) {
        const float* r = f + p + 128;
        if (x > 0   && v < __ldg(r - 1)) return false;
        if (           v < __ldg(r))     return false;
        if (x < 127 && v < __ldg(r + 1)) return false;
    }
    return true;
}

__device__ __forceinline__ void bitonic_sort_desc(u64* keys, int n, int tid, int nth) {
    for (int k = 2; k <= n; k <<= 1) {
        for (int j = k >> 1; j > 0; j >>= 1) {
            for (int i = tid; i < n; i += nth) {
                int l = i ^ j;
                if (l > i) {
                    u64 a = keys[i], b = keys[l];
                    bool desc = ((i & k) == 0);
                    if (desc ? (a < b) : (a > b)) { keys[i] = b; keys[l] = a; }
                }
            }
            __syncthreads();
        }
    }
}

// Descending scan over 2048 bins: T s.t. count(bins>T) < need <= count(bins>=T).
// Requires blockDim.x == 512. Ends with __syncthreads.
__device__ void hist_threshold(const u32* hist, int need, int tid, int* sh_T, int* sh_above) {
    __shared__ int warp_pref[16];
    int base = 2047 - 4 * tid;
    int h0 = hist[base], h1 = hist[base - 1], h2 = hist[base - 2], h3 = hist[base - 3];
    int gs = h0 + h1 + h2 + h3;
    int lane = tid & 31, w = tid >> 5;
    int v = gs;
    #pragma unroll
    for (int off = 1; off < 32; off <<= 1) {
        int u = __shfl_up_sync(0xffffffffu, v, off);
        if (lane >= off) v += u;
    }
    if (lane == 31) warp_pref[w] = v;
    __syncthreads();
    if (w == 0) {
        int x = (lane < 16) ? warp_pref[lane] : 0;
        #pragma unroll
        for (int off = 1; off < 16; off <<= 1) {
            int u = __shfl_up_sync(0xffffffffu, x, off);
            if (lane >= off) x += u;
        }
        if (lane < 16) warp_pref[lane] = x;
    }
    __syncthreads();
    int pref = v + (w ? warp_pref[w - 1] : 0);   // count of bins >= base-3
    int before = pref - gs;                       // count of bins >  base
    if (pref >= need && before < need) {
        int run = before;
        int hh[4] = {h0, h1, h2, h3};
        #pragma unroll
        for (int i = 0; i < 4; i++) {
            if (run + hh[i] >= need) { *sh_T = base - i; *sh_above = run; break; }
            run += hh[i];
        }
    }
    if (tid == 511 && pref < need) { *sh_T = 0; *sh_above = pref - h3; }
    __syncthreads();
}

// ---------------------------------------------------------------------------
__global__ void k_init() {
    if (threadIdx.x < NB) g_cnt[threadIdx.x] = 0;
}

// ---------------------------------------------------------------------------
// K1: screen. One coalesced pass over fmap; rare exact NMS for points >= TAU0.
// Grid = B*C = 2560 blocks x 512 threads.
// ---------------------------------------------------------------------------
__global__ void __launch_bounds__(512) k_screen(const float* __restrict__ fmap) {
    const int bc = blockIdx.x;
    const int b = bc / NC;
    const int c = bc - b * NC;
    const float* __restrict__ f = fmap + (size_t)bc * NHW;
    const float4* __restrict__ f4 = (const float4*)f;

    #pragma unroll
    for (int k = 0; k < (NHW / 4) / 512; k++) {
        const int i = threadIdx.x + k * 512;
        float4 v = __ldg(f4 + i);
        float m = fmaxf(fmaxf(v.x, v.y), fmaxf(v.z, v.w));
        if (m >= TAU0) {
            float vv[4] = {v.x, v.y, v.z, v.w};
            #pragma unroll
            for (int e = 0; e < 4; e++) {
                if (vv[e] >= TAU0) {
                    int p = i * 4 + e;
                    if (nms_keep(f, p, vv[e])) {
                        int pos = atomicAdd(&g_cnt[b], 1);
                        if (pos < GCAP)
                            g_cand[(size_t)b * GCAP + pos] = make_key(vv[e], c, p);
                    }
                }
            }
        }
    }
}

// ---------------------------------------------------------------------------
// K2: per-batch sort of candidates + decode. Grid = B = 32 blocks x 512.
// smem: keys[8192] u64 (64K) + hist[2048] u32 (8K) = 72K
// Fallback (never taken for this data): adaptive radix threshold over ALL
// survivors of the batch, recollect into g_cand, then same sort+decode.
// ---------------------------------------------------------------------------
__global__ void __launch_bounds__(512) k_select(const float* __restrict__ fmap,
                                                const float* __restrict__ wh,
                                                const float* __restrict__ reg,
                                                float* __restrict__ out) {
    u64* keys = (u64*)smem_raw;
    u32* hist = (u32*)(keys + GCAP);
    __shared__ int sh_T, sh_above;

    const int b = blockIdx.x;
    const int tid = threadIdx.x;
    int cnt = g_cnt[b];

    if (cnt < NK || cnt > GCAP) {
        // ---- slow exact fallback ----
        const float* fb = fmap + (size_t)b * NC * NHW;
        u32 prefix = 0;
        u32 tau = 0;
        int need = NK;
        long long total_above = 0;
        const int shifts[3] = {21, 10, 0};

        for (int lvl = 0; lvl < 3; lvl++) {
            for (int i = tid; i < 2048; i += 512) hist[i] = 0;
            __syncthreads();
            const int sh = shifts[lvl];
            for (int t = tid; t < NC * NHW; t += 512) {
                int c = t >> 14, p = t & (NHW - 1);
                const float* f = fb + (size_t)c * NHW;
                float v = __ldg(f + p);
                u32 o = ord32(v);
                bool inwin = (lvl == 0) ||
                             ((o >> shifts[lvl - 1]) == (prefix >> shifts[lvl - 1]));
                if (inwin && nms_keep(f, p, v)) {
                    u32 bin = (o >> sh) & ((lvl == 2) ? 0x3FFu : 0x7FFu);
                    atomicAdd(&hist[bin], 1);
                }
            }
            __syncthreads();
            hist_threshold(hist, need, tid, &sh_T, &sh_above);
            int T = sh_T, above = sh_above;
            long long candc = total_above + above + (long long)hist[T];
            tau = prefix | ((u32)T << sh);
            if (candc <= GCAP || lvl == 2) break;
            prefix |= (u32)T << sh;
            need -= above;
            total_above += above;
            __syncthreads();
        }

        if (tid == 0) g_cnt[b] = 0;
        __syncthreads();
        for (int t = tid; t < NC * NHW; t += 512) {
            int c = t >> 14, p = t & (NHW - 1);
            const float* f = fb + (size_t)c * NHW;
            float v = __ldg(f + p);
            u32 o = ord32(v);
            if (o >= tau && nms_keep(f, p, v)) {
                int pos = atomicAdd(&g_cnt[b], 1);
                if (pos < GCAP) g_cand[(size_t)b * GCAP + pos] = make_key(v, c, p);
            }
        }
        __syncthreads();
        cnt = g_cnt[b];
        if (cnt > GCAP) cnt = GCAP;
    }

    // ---- common tail: sort + decode ----
    int npad = 128;
    while (npad < cnt) npad <<= 1;   // <= GCAP
    for (int i = tid; i < npad; i += 512)
        keys[i] = (i < cnt) ? g_cand[(size_t)b * GCAP + i] : 0ULL;
    __syncthreads();

    bitonic_sort_desc(keys, npad, tid, 512);

    if (tid < NK) {
        u64 key = keys[tid];
        float sc = 0.f, bx0 = 0.f, by0 = 0.f, bx1 = 0.f, by1 = 0.f, cls = 0.f;
        if (key != 0ULL) {
            u32 o = (u32)(key >> 32);
            sc = ord_inv(o);
            u32 rec = (u32)key & 0x1FFFFFu;
            int c = NC - 1 - (int)(rec >> 14);
            int p = NHW - 1 - (int)(rec & 0x3FFFu);
            const float* whb = wh + (size_t)b * 2 * NHW;
            const float* rgb = reg + (size_t)b * 2 * NHW;
            float ys = (float)(p >> 7);
            float xs = (float)(p & 127);
            float xc = xs + __ldg(rgb + p);
            float yc = ys + __ldg(rgb + NHW + p);
            float hw2 = 0.5f * __ldg(whb + p);
            float hh2 = 0.5f * __ldg(whb + NHW + p);
            bx0 = xc - hw2; by0 = yc - hh2; bx1 = xc + hw2; by1 = yc + hh2;
            cls = (float)c;
        }
        size_t bb = ((size_t)b * NK + tid) * 4;
        out[bb + 0] = bx0;
        out[bb + 1] = by0;
        out[bb + 2] = bx1;
        out[bb + 3] = by1;
        out[(size_t)NB * NK * 4 + (size_t)b * NK + tid] = sc;
        out[(size_t)NB * NK * 5 + (size_t)b * NK + tid] = cls;
    }
}

extern "C" void kernel_launch(void* const* d_in, const int* in_sizes, int n_in,
                              void* d_out, int out_size) {
    const float* fmap = (const float*)d_in[0];
    const float* wh   = (const float*)d_in[1];
    const float* reg  = (const float*)d_in[2];
    float* out = (float*)d_out;

    const size_t smem2 = GCAP * sizeof(u64) + 2048 * sizeof(u32);  // 72 KB

    static bool attr_done = false;
    if (!attr_done) {
        cudaFuncSetAttribute(k_select, cudaFuncAttributeMaxDynamicSharedMemorySize, (int)smem2);
        attr_done = true;
    }

    k_init<<<1, 32>>>();
    k_screen<<<NB * NC, 512>>>(fmap);
    k_select<<<NB, 512, smem2>>>(fmap, wh, reg, out);
}

// round 5
// speedup vs baseline: 13.0709x; 1.8136x over previous
#include <cuda_runtime.h>

// CenterNet decode, sm_100a.
// d_in[0]=fmap f32 [32,80,128,128], d_in[1]=wh f32 [32,2,128,128],
// d_in[2]=reg f32 [32,2,128,128], d_in[3]=K (=100)
// out f32: concat(bboxes[32,100,4], scores[32,100,1], clses[32,100,1]) = 19200

#define NB 32
#define NC 80
#define NHW 16384
#define NK 100
#define GCAP 8192
#define TAU0 0.9998f

#define SCR_BLOCKS 592          // 148 SMs x 4 blocks -> exactly one wave
#define SCR_THREADS 512
#define SCR_ILP 8
#define TOT4 (NB * NC * (NHW / 4))   // 10,485,760 float4s

typedef unsigned long long u64;
typedef unsigned int u32;

__device__ u64 g_cand[NB * GCAP];
__device__ int g_cnt[NB];        // zero at module load; k_select re-zeros at end

extern __shared__ unsigned char smem_raw[];

// monotone float->uint mapping
__device__ __forceinline__ u32 ord32(float f) {
    u32 b = __float_as_uint(f);
    return b ^ ((u32)((int)b >> 31) | 0x80000000u);
}
__device__ __forceinline__ float ord_inv(u32 o) {
    u32 b = (o & 0x80000000u) ? (o ^ 0x80000000u) : ~o;
    return __uint_as_float(b);
}
// key: (score desc, class asc, spatial idx asc) as one descending u64
__device__ __forceinline__ u64 make_key(float v, int c, int p) {
    return ((u64)ord32(v) << 32) |
           (u32)(((NC - 1 - c) << 14) | (NHW - 1 - p));
}

// keep iff v >= all in-bounds 8-neighbors (== maxpool3x3(-inf pad) == v)
__device__ __forceinline__ bool nms_keep(const float* __restrict__ f, int p, float v) {
    const int y = p >> 7, x = p & 127;
    if (y > 0) {
        const float* r = f + p - 128;
        if (x > 0   && v < __ldg(r - 1)) return false;
        if (           v < __ldg(r))     return false;
        if (x < 127 && v < __ldg(r + 1)) return false;
    }
    if (x > 0   && v < __ldg(f + p - 1)) return false;
    if (x < 127 && v < __ldg(f + p + 1)) return false;
    if (y < 127) {
        const float* r = f + p + 128;
        if (x > 0   && v < __ldg(r - 1)) return false;
        if (           v < __ldg(r))     return false;
        if (x < 127 && v < __ldg(r + 1)) return false;
    }
    return true;
}

__device__ __forceinline__ void bitonic_sort_desc(u64* keys, int n, int tid, int nth) {
    for (int k = 2; k <= n; k <<= 1) {
        for (int j = k >> 1; j > 0; j >>= 1) {
            for (int i = tid; i < n; i += nth) {
                int l = i ^ j;
                if (l > i) {
                    u64 a = keys[i], b = keys[l];
                    bool desc = ((i & k) == 0);
                    if (desc ? (a < b) : (a > b)) { keys[i] = b; keys[l] = a; }
                }
            }
            __syncthreads();
        }
    }
}

// Descending scan over 2048 bins. Requires blockDim.x == 512.
__device__ void hist_threshold(const u32* hist, int need, int tid, int* sh_T, int* sh_above) {
    __shared__ int warp_pref[16];
    int base = 2047 - 4 * tid;
    int h0 = hist[base], h1 = hist[base - 1], h2 = hist[base - 2], h3 = hist[base - 3];
    int gs = h0 + h1 + h2 + h3;
    int lane = tid & 31, w = tid >> 5;
    int v = gs;
    #pragma unroll
    for (int off = 1; off < 32; off <<= 1) {
        int u = __shfl_up_sync(0xffffffffu, v, off);
        if (lane >= off) v += u;
    }
    if (lane == 31) warp_pref[w] = v;
    __syncthreads();
    if (w == 0) {
        int x = (lane < 16) ? warp_pref[lane] : 0;
        #pragma unroll
        for (int off = 1; off < 16; off <<= 1) {
            int u = __shfl_up_sync(0xffffffffu, x, off);
            if (lane >= off) x += u;
        }
        if (lane < 16) warp_pref[lane] = x;
    }
    __syncthreads();
    int pref = v + (w ? warp_pref[w - 1] : 0);
    int before = pref - gs;
    if (pref >= need && before < need) {
        int run = before;
        int hh[4] = {h0, h1, h2, h3};
        #pragma unroll
        for (int i = 0; i < 4; i++) {
            if (run + hh[i] >= need) { *sh_T = base - i; *sh_above = run; break; }
            run += hh[i];
        }
    }
    if (tid == 511 && pref < need) { *sh_T = 0; *sh_above = pref - h3; }
    __syncthreads();
}

// ---------------------------------------------------------------------------
// K1: screen. Grid-stride ILP-8 coalesced float4 pass; rare exact NMS for
// points >= TAU0. Grid = 592 x 512 (one full wave).
// ---------------------------------------------------------------------------
__global__ void __launch_bounds__(SCR_THREADS) k_screen(const float* __restrict__ fmap) {
    const float4* __restrict__ f4 = (const float4*)fmap;
    const int gtid = blockIdx.x * SCR_THREADS + threadIdx.x;
    const int NT = SCR_BLOCKS * SCR_THREADS;

    for (int base = gtid; base < TOT4; base += NT * SCR_ILP) {
        float4 v[SCR_ILP];
        // front-batched independent loads (predicated on bounds)
        #pragma unroll
        for (int k = 0; k < SCR_ILP; k++) {
            int idx = base + k * NT;
            v[k] = (idx < TOT4) ? __ldg(f4 + idx) : make_float4(0.f, 0.f, 0.f, 0.f);
        }
        float m[SCR_ILP];
        float mall = 0.f;
        #pragma unroll
        for (int k = 0; k < SCR_ILP; k++) {
            m[k] = fmaxf(fmaxf(v[k].x, v[k].y), fmaxf(v[k].z, v[k].w));
            mall = fmaxf(mall, m[k]);
        }
        if (mall >= TAU0) {
            #pragma unroll
            for (int k = 0; k < SCR_ILP; k++) {
                if (m[k] >= TAU0) {
                    int idx = base + k * NT;
                    if (idx < TOT4) {
                        int bc = idx >> 12;           // NHW/4 = 4096 per slice
                        int p4 = idx & 4095;
                        int b = bc / NC;
                        int c = bc - b * NC;
                        const float* f = fmap + (size_t)bc * NHW;
                        float vv[4] = {v[k].x, v[k].y, v[k].z, v[k].w};
                        #pragma unroll
                        for (int e = 0; e < 4; e++) {
                            if (vv[e] >= TAU0) {
                                int p = p4 * 4 + e;
                                if (nms_keep(f, p, vv[e])) {
                                    int pos = atomicAdd(&g_cnt[b], 1);
                                    if (pos < GCAP)
                                        g_cand[(size_t)b * GCAP + pos] = make_key(vv[e], c, p);
                                }
                            }
                        }
                    }
                }
            }
        }
    }
}

// ---------------------------------------------------------------------------
// K2: per-batch sort of candidates + decode. Grid = B = 32 blocks x 512.
// smem: keys[8192] u64 (64K) + hist[2048] u32 (8K) = 72K.
// Fallback (never taken for this data): exact adaptive radix threshold over
// all NMS survivors of the batch, recollect, then same sort+decode.
// Resets g_cnt[b] at the end so the next call starts clean (no init kernel).
// ---------------------------------------------------------------------------
__global__ void __launch_bounds__(512) k_select(const float* __restrict__ fmap,
                                                const float* __restrict__ wh,
                                                const float* __restrict__ reg,
                                                float* __restrict__ out) {
    u64* keys = (u64*)smem_raw;
    u32* hist = (u32*)(keys + GCAP);
    __shared__ int sh_T, sh_above;

    const int b = blockIdx.x;
    const int tid = threadIdx.x;
    int cnt = g_cnt[b];

    if (cnt < NK || cnt > GCAP) {
        // ---- slow exact fallback ----
        const float* fb = fmap + (size_t)b * NC * NHW;
        u32 prefix = 0;
        u32 tau = 0;
        int need = NK;
        long long total_above = 0;
        const int shifts[3] = {21, 10, 0};

        for (int lvl = 0; lvl < 3; lvl++) {
            for (int i = tid; i < 2048; i += 512) hist[i] = 0;
            __syncthreads();
            const int sh = shifts[lvl];
            for (int t = tid; t < NC * NHW; t += 512) {
                int c = t >> 14, p = t & (NHW - 1);
                const float* f = fb + (size_t)c * NHW;
                float v = __ldg(f + p);
                u32 o = ord32(v);
                bool inwin = (lvl == 0) ||
                             ((o >> shifts[lvl - 1]) == (prefix >> shifts[lvl - 1]));
                if (inwin && nms_keep(f, p, v)) {
                    u32 bin = (o >> sh) & ((lvl == 2) ? 0x3FFu : 0x7FFu);
                    atomicAdd(&hist[bin], 1);
                }
            }
            __syncthreads();
            hist_threshold(hist, need, tid, &sh_T, &sh_above);
            int T = sh_T, above = sh_above;
            long long candc = total_above + above + (long long)hist[T];
            tau = prefix | ((u32)T << sh);
            if (candc <= GCAP || lvl == 2) break;
            prefix |= (u32)T << sh;
            need -= above;
            total_above += above;
            __syncthreads();
        }

        if (tid == 0) g_cnt[b] = 0;
        __syncthreads();
        for (int t = tid; t < NC * NHW; t += 512) {
            int c = t >> 14, p = t & (NHW - 1);
            const float* f = fb + (size_t)c * NHW;
            float v = __ldg(f + p);
            u32 o = ord32(v);
            if (o >= tau && nms_keep(f, p, v)) {
                int pos = atomicAdd(&g_cnt[b], 1);
                if (pos < GCAP) g_cand[(size_t)b * GCAP + pos] = make_key(v, c, p);
            }
        }
        __syncthreads();
        cnt = g_cnt[b];
        if (cnt > GCAP) cnt = GCAP;
    }

    // ---- common tail: sort + decode ----
    int npad = 128;
    while (npad < cnt) npad <<= 1;   // <= GCAP
    for (int i = tid; i < npad; i += 512)
        keys[i] = (i < cnt) ? g_cand[(size_t)b * GCAP + i] : 0ULL;
    __syncthreads();

    bitonic_sort_desc(keys, npad, tid, 512);

    if (tid < NK) {
        u64 key = keys[tid];
        float sc = 0.f, bx0 = 0.f, by0 = 0.f, bx1 = 0.f, by1 = 0.f, cls = 0.f;
        if (key != 0ULL) {
            u32 o = (u32)(key >> 32);
            sc = ord_inv(o);
            u32 rec = (u32)key & 0x1FFFFFu;
            int c = NC - 1 - (int)(rec >> 14);
            int p = NHW - 1 - (int)(rec & 0x3FFFu);
            const float* whb = wh + (size_t)b * 2 * NHW;
            const float* rgb = reg + (size_t)b * 2 * NHW;
            float ys = (float)(p >> 7);
            float xs = (float)(p & 127);
            float xc = xs + __ldg(rgb + p);
            float yc = ys + __ldg(rgb + NHW + p);
            float hw2 = 0.5f * __ldg(whb + p);
            float hh2 = 0.5f * __ldg(whb + NHW + p);
            bx0 = xc - hw2; by0 = yc - hh2; bx1 = xc + hw2; by1 = yc + hh2;
            cls = (float)c;
        }
        size_t bb = ((size_t)b * NK + tid) * 4;
        out[bb + 0] = bx0;
        out[bb + 1] = by0;
        out[bb + 2] = bx1;
        out[bb + 3] = by1;
        out[(size_t)NB * NK * 4 + (size_t)b * NK + tid] = sc;
        out[(size_t)NB * NK * 5 + (size_t)b * NK + tid] = cls;
    }

    // reset counter for the next invocation (globals start zeroed at load)
    __syncthreads();
    if (tid == 0) g_cnt[b] = 0;
}

extern "C" void kernel_launch(void* const* d_in, const int* in_sizes, int n_in,
                              void* d_out, int out_size) {
    const float* fmap = (const float*)d_in[0];
    const float* wh   = (const float*)d_in[1];
    const float* reg  = (const float*)d_in[2];
    float* out = (float*)d_out;

    const size_t smem2 = GCAP * sizeof(u64) + 2048 * sizeof(u32);  // 72 KB

    static bool attr_done = false;
    if (!attr_done) {
        cudaFuncSetAttribute(k_select, cudaFuncAttributeMaxDynamicSharedMemorySize, (int)smem2);
        attr_done = true;
    }

    k_screen<<<SCR_BLOCKS, SCR_THREADS>>>(fmap);
    k_select<<<NB, 512, smem2>>>(fmap, wh, reg, out);
}